// round 3
// baseline (speedup 1.0000x reference)
#include <cuda_runtime.h>

#define HID 64
#define NMAX 100352
#define EMAX 3210240

// ---------------- scratch (static device globals; no allocation) ----------------
__device__ int   g_deg[NMAX];
__device__ int   g_off[NMAX + 1];
__device__ int   g_rank[EMAX];
__device__ int   g_adj[EMAX];
__device__ float g_spos[NMAX];
__device__ float g_sneg[NMAX];
__device__ __align__(16) float g_aggr[NMAX * HID];
__device__ __align__(16) float g_x0[NMAX * HID];
__device__ __align__(16) float g_x1[NMAX * HID];
__device__ float g_sumx[HID];
__device__ float g_c[1];

// ---------------- init ----------------
__global__ void k_zero(int n) {
    int i = blockIdx.x * blockDim.x + threadIdx.x;
    int stride = gridDim.x * blockDim.x;
    for (int j = i; j < n; j += stride) {
        g_deg[j]  = 0;
        g_spos[j] = 0.f;
        g_sneg[j] = 0.f;
    }
    if (i < HID) g_sumx[i] = 0.f;
}

// ---------------- edge pass: degree histogram (returns rank) + p3 scalars ----------------
__global__ void k_hist(const int* __restrict__ src, const int* __restrict__ dst,
                       const float* __restrict__ attr, int E) {
    int i = blockIdx.x * blockDim.x + threadIdx.x;
    int stride = gridDim.x * blockDim.x;
    for (int e = i; e < E; e += stride) {
        int d = dst[e];
        g_rank[e] = atomicAdd(&g_deg[d], 1);
        float a = attr[e];
        int s = src[e];
        if (a >= 0.f) atomicAdd(&g_spos[s], a);
        else          atomicAdd(&g_sneg[s], -a);
    }
}

// ---------------- single-block exclusive scan over degrees -> CSR offsets ----------------
__global__ void k_scan(int n) {
    __shared__ int warp_sums[32];
    __shared__ int s_carry;
    int tid = threadIdx.x, lane = tid & 31, wid = tid >> 5;
    if (tid == 0) s_carry = 0;
    __syncthreads();
    for (int base = 0; base < n; base += 1024) {
        int idx = base + tid;
        int v = (idx < n) ? g_deg[idx] : 0;
        int x = v;
        #pragma unroll
        for (int o = 1; o < 32; o <<= 1) {
            int t = __shfl_up_sync(0xffffffffu, x, o);
            if (lane >= o) x += t;
        }
        if (lane == 31) warp_sums[wid] = x;
        __syncthreads();
        if (wid == 0) {
            int w = warp_sums[lane];
            #pragma unroll
            for (int o = 1; o < 32; o <<= 1) {
                int t = __shfl_up_sync(0xffffffffu, w, o);
                if (lane >= o) w += t;
            }
            warp_sums[lane] = w;
        }
        __syncthreads();
        int pre = (wid > 0) ? warp_sums[wid - 1] : 0;
        int incl = x + pre;
        int old_carry = s_carry;
        if (idx < n) g_off[idx] = old_carry + incl - v;  // exclusive
        __syncthreads();
        if (tid == 0) s_carry = old_carry + warp_sums[31];
        __syncthreads();
    }
    if (threadIdx.x == 0) g_off[n] = s_carry;
}

// ---------------- atomic-free CSR fill using precomputed ranks ----------------
__global__ void k_scatter(const int* __restrict__ src, const int* __restrict__ dst, int E) {
    int i = blockIdx.x * blockDim.x + threadIdx.x;
    int stride = gridDim.x * blockDim.x;
    for (int e = i; e < E; e += stride) {
        int d = dst[e];
        g_adj[g_off[d] + g_rank[e]] = src[e];
    }
}

// ---------------- gather-side aggregation: one warp per node ----------------
__global__ void k_aggr(const float* __restrict__ xext, int which, int n) {
    int node = (blockIdx.x * blockDim.x + threadIdx.x) >> 5;
    if (node >= n) return;
    int lane = threadIdx.x & 31;
    const float* xin = (which == 0) ? xext : ((which == 1) ? g_x0 : g_x1);
    const float2* xf2 = (const float2*)xin;
    int s = g_off[node], e = g_off[node + 1];
    float2 acc = make_float2(0.f, 0.f);
    int k = s;
    for (; k + 4 <= e; k += 4) {
        int j0 = g_adj[k], j1 = g_adj[k + 1], j2 = g_adj[k + 2], j3 = g_adj[k + 3];
        float2 a = xf2[j0 * 32 + lane];
        float2 b = xf2[j1 * 32 + lane];
        float2 c = xf2[j2 * 32 + lane];
        float2 d = xf2[j3 * 32 + lane];
        acc.x += (a.x + b.x) + (c.x + d.x);
        acc.y += (a.y + b.y) + (c.y + d.y);
    }
    for (; k < e; ++k) {
        float2 a = xf2[g_adj[k] * 32 + lane];
        acc.x += a.x; acc.y += a.y;
    }
    ((float2*)g_aggr)[node * 32 + lane] = acc;
}

// ---------------- fused round GEMM: xnew = relu(p1 + aggr@W2 + p3) ----------------
#define FMA4(AS, BV, ACC) \
    ACC[0] = fmaf(AS, BV.x, ACC[0]); \
    ACC[1] = fmaf(AS, BV.y, ACC[1]); \
    ACC[2] = fmaf(AS, BV.z, ACC[2]); \
    ACC[3] = fmaf(AS, BV.w, ACC[3]);

__global__ __launch_bounds__(256) void k_round(
    const float* __restrict__ xtag,
    const float* __restrict__ W1l, const float* __restrict__ W2l, const float* __restrict__ W4l,
    int which_out, int n, int do_sum)
{
    __shared__ __align__(16) float Bs[HID * HID];
    __shared__ __align__(16) float As[HID * HID];
    __shared__ float p1w[HID], p3p[HID], p3n[HID];
    float* xout = which_out ? g_x1 : g_x0;

    int tid = threadIdx.x;
    for (int i = tid; i < HID * HID; i += 256) Bs[i] = W2l[i];
    if (tid < HID) {
        p1w[tid] = W1l[tid];
        float w = W4l[tid];
        p3p[tid] = fmaxf(w, 0.f);
        p3n[tid] = fmaxf(-w, 0.f);
    }
    __syncthreads();

    int tx = tid & 15, ty = tid >> 4;
    int h0 = tx * 4, m0 = ty * 4;
    float4* As4 = (float4*)As;
    float4* Bs4 = (float4*)Bs;
    float psum[4] = {0.f, 0.f, 0.f, 0.f};
    int ntiles = (n + 63) >> 6;

    for (int tile = blockIdx.x; tile < ntiles; tile += gridDim.x) {
        int base = tile << 6;
        const float4* Ag = (const float4*)g_aggr + base * 16;
        int avail4 = (((n - base) < 64) ? (n - base) : 64) * 16;
        for (int i = tid; i < 1024; i += 256)
            As4[i] = (i < avail4) ? Ag[i] : make_float4(0.f, 0.f, 0.f, 0.f);
        __syncthreads();

        float acc[4][4];
        #pragma unroll
        for (int i = 0; i < 4; ++i)
            #pragma unroll
            for (int j = 0; j < 4; ++j) acc[i][j] = 0.f;

        #pragma unroll
        for (int k4 = 0; k4 < 16; ++k4) {
            float4 b0 = Bs4[(4 * k4 + 0) * 16 + tx];
            float4 b1 = Bs4[(4 * k4 + 1) * 16 + tx];
            float4 b2 = Bs4[(4 * k4 + 2) * 16 + tx];
            float4 b3 = Bs4[(4 * k4 + 3) * 16 + tx];
            #pragma unroll
            for (int i = 0; i < 4; ++i) {
                float4 a = As4[(m0 + i) * 16 + k4];
                FMA4(a.x, b0, acc[i]);
                FMA4(a.y, b1, acc[i]);
                FMA4(a.z, b2, acc[i]);
                FMA4(a.w, b3, acc[i]);
            }
        }

        #pragma unroll
        for (int i = 0; i < 4; ++i) {
            int m = base + m0 + i;
            if (m < n) {
                float t = xtag[m], sp = g_spos[m], sn = g_sneg[m];
                float4 o;
                o.x = fmaxf(acc[i][0] + t * p1w[h0 + 0] + sp * p3p[h0 + 0] + sn * p3n[h0 + 0], 0.f);
                o.y = fmaxf(acc[i][1] + t * p1w[h0 + 1] + sp * p3p[h0 + 1] + sn * p3n[h0 + 1], 0.f);
                o.z = fmaxf(acc[i][2] + t * p1w[h0 + 2] + sp * p3p[h0 + 2] + sn * p3n[h0 + 2], 0.f);
                o.w = fmaxf(acc[i][3] + t * p1w[h0 + 3] + sp * p3p[h0 + 3] + sn * p3n[h0 + 3], 0.f);
                ((float4*)xout)[m * 16 + tx] = o;
                psum[0] += o.x; psum[1] += o.y; psum[2] += o.z; psum[3] += o.w;
            }
        }
        __syncthreads();
    }

    if (do_sum) {
        // reduce psum across the 16 ty-groups, then one atomic per h per block
        As[ty * HID + h0 + 0] = psum[0];
        As[ty * HID + h0 + 1] = psum[1];
        As[ty * HID + h0 + 2] = psum[2];
        As[ty * HID + h0 + 3] = psum[3];
        __syncthreads();
        if (tid < HID) {
            float s = 0.f;
            #pragma unroll
            for (int w = 0; w < 16; ++w) s += As[w * HID + tid];
            atomicAdd(&g_sumx[tid], s);
        }
    }
}

// ---------------- graph-pool scalar: c = sum_h relu((sumx @ W6)[h]) * W5[h] ----------------
__global__ void k_gpool(const float* __restrict__ W6, const float* __restrict__ W5) {
    int h = threadIdx.x;  // 64 threads
    float g = 0.f;
    #pragma unroll
    for (int k = 0; k < HID; ++k) g = fmaf(g_sumx[k], W6[k * HID + h], g);
    float v = fmaxf(g, 0.f) * W5[h];
    __shared__ float sh[HID];
    sh[h] = v;
    __syncthreads();
    if (h < 32) {
        float t = sh[h] + sh[h + 32];
        #pragma unroll
        for (int o = 16; o > 0; o >>= 1) t += __shfl_down_sync(0xffffffffu, t, o);
        if (h == 0) g_c[0] = t;
    }
}

// ---------------- final: Q[i] = c + sum_h relu((x @ W7)[i,h]) * W5[64+h] ----------------
__global__ __launch_bounds__(256) void k_final(
    const float* __restrict__ W7, const float* __restrict__ W5,
    float* __restrict__ Q, int n)
{
    __shared__ __align__(16) float Bs[HID * HID];
    __shared__ __align__(16) float As[HID * HID];
    __shared__ float w5s[HID];
    int tid = threadIdx.x;
    for (int i = tid; i < HID * HID; i += 256) Bs[i] = W7[i];
    if (tid < HID) w5s[tid] = W5[HID + tid];
    __syncthreads();

    int tx = tid & 15, ty = tid >> 4;
    int h0 = tx * 4, m0 = ty * 4;
    float4* As4 = (float4*)As;
    float4* Bs4 = (float4*)Bs;
    int ntiles = (n + 63) >> 6;
    float c = g_c[0];

    for (int tile = blockIdx.x; tile < ntiles; tile += gridDim.x) {
        int base = tile << 6;
        const float4* Ag = (const float4*)g_x1 + base * 16;
        int avail4 = (((n - base) < 64) ? (n - base) : 64) * 16;
        for (int i = tid; i < 1024; i += 256)
            As4[i] = (i < avail4) ? Ag[i] : make_float4(0.f, 0.f, 0.f, 0.f);
        __syncthreads();

        float acc[4][4];
        #pragma unroll
        for (int i = 0; i < 4; ++i)
            #pragma unroll
            for (int j = 0; j < 4; ++j) acc[i][j] = 0.f;

        #pragma unroll
        for (int k4 = 0; k4 < 16; ++k4) {
            float4 b0 = Bs4[(4 * k4 + 0) * 16 + tx];
            float4 b1 = Bs4[(4 * k4 + 1) * 16 + tx];
            float4 b2 = Bs4[(4 * k4 + 2) * 16 + tx];
            float4 b3 = Bs4[(4 * k4 + 3) * 16 + tx];
            #pragma unroll
            for (int i = 0; i < 4; ++i) {
                float4 a = As4[(m0 + i) * 16 + k4];
                FMA4(a.x, b0, acc[i]);
                FMA4(a.y, b1, acc[i]);
                FMA4(a.z, b2, acc[i]);
                FMA4(a.w, b3, acc[i]);
            }
        }

        #pragma unroll
        for (int i = 0; i < 4; ++i) {
            int m = base + m0 + i;
            float part = fmaxf(acc[i][0], 0.f) * w5s[h0 + 0]
                       + fmaxf(acc[i][1], 0.f) * w5s[h0 + 1]
                       + fmaxf(acc[i][2], 0.f) * w5s[h0 + 2]
                       + fmaxf(acc[i][3], 0.f) * w5s[h0 + 3];
            // reduce across the 16 tx lanes sharing this node (xor<16 stays in half-warp)
            #pragma unroll
            for (int o = 8; o > 0; o >>= 1) part += __shfl_xor_sync(0xffffffffu, part, o);
            if (tx == 0 && m < n) Q[m] = c + part;
        }
        __syncthreads();
    }
}

// ---------------- launcher ----------------
extern "C" void kernel_launch(void* const* d_in, const int* in_sizes, int n_in,
                              void* d_out, int out_size) {
    const float* x     = (const float*)d_in[0];
    const float* xtag  = (const float*)d_in[1];
    const float* eattr = (const float*)d_in[2];
    const int*   eidx  = (const int*)d_in[3];
    const float* W1    = (const float*)d_in[4];
    const float* W2    = (const float*)d_in[5];
    const float* W4    = (const float*)d_in[6];
    const float* W5    = (const float*)d_in[7];
    const float* W6    = (const float*)d_in[8];
    const float* W7    = (const float*)d_in[9];
    float* Q = (float*)d_out;

    int n = in_sizes[1];
    int E = in_sizes[2];
    const int* src = eidx;
    const int* dst = eidx + E;

    int gb_n = (n + 255) / 256;
    int gb_e = (E + 255) / 256;
    int gb_w = (n * 32 + 255) / 256;   // warp-per-node
    int gb_g = 782;                     // GEMM grid (grid-stride over 64-node tiles)

    // CSR build + p3 scalars (once per launch)
    k_zero<<<gb_n, 256>>>(n);
    k_hist<<<gb_e, 256>>>(src, dst, eattr, E);
    k_scan<<<1, 1024>>>(n);
    k_scatter<<<gb_e, 256>>>(src, dst, E);

    // 4 propagation rounds (ping-pong: ext -> x0 -> x1 -> x0 -> x1)
    k_aggr<<<gb_w, 256>>>(x, 0, n);
    k_round<<<gb_g, 256>>>(xtag, W1 + 0 * HID, W2 + 0 * HID * HID, W4 + 0 * HID, 0, n, 0);
    k_aggr<<<gb_w, 256>>>(x, 1, n);
    k_round<<<gb_g, 256>>>(xtag, W1 + 1 * HID, W2 + 1 * HID * HID, W4 + 1 * HID, 1, n, 0);
    k_aggr<<<gb_w, 256>>>(x, 2, n);
    k_round<<<gb_g, 256>>>(xtag, W1 + 2 * HID, W2 + 2 * HID * HID, W4 + 2 * HID, 0, n, 0);
    k_aggr<<<gb_w, 256>>>(x, 1, n);
    k_round<<<gb_g, 256>>>(xtag, W1 + 3 * HID, W2 + 3 * HID * HID, W4 + 3 * HID, 1, n, 1);

    // readout
    k_gpool<<<1, HID>>>(W6, W5);
    k_final<<<gb_g, 256>>>(W7, W5, Q, n);
}

// round 4
// speedup vs baseline: 1.2597x; 1.2597x over previous
#include <cuda_runtime.h>
#include <cuda_bf16.h>

#define HID 64
#define NMAX 100352
#define EMAX 3210240

// ---------------- scratch (static device globals; no allocation) ----------------
__device__ int   g_deg[NMAX];
__device__ int   g_off[NMAX + 1];
__device__ int   g_bsum[512];
__device__ int   g_rank[EMAX];
__device__ int   g_adj[EMAX];
__device__ float g_spos[NMAX];
__device__ float g_sneg[NMAX];
__device__ __align__(16) float g_aggr[NMAX * HID];
__device__ __align__(16) float g_x4[NMAX * HID];                 // round-4 output (fp32)
__device__ __align__(16) __nv_bfloat16 g_h0[NMAX * HID];          // bf16 x buffers
__device__ __align__(16) __nv_bfloat16 g_h1[NMAX * HID];
__device__ __align__(16) __nv_bfloat16 g_h2[NMAX * HID];
__device__ float g_sumx[HID];
__device__ float g_c[1];

// exact bf16x2 -> float2 (bits<<16)
__device__ __forceinline__ float2 bf2_to_f2(unsigned u) {
    float2 r;
    r.x = __uint_as_float(u << 16);
    r.y = __uint_as_float(u & 0xFFFF0000u);
    return r;
}

// ---------------- init ----------------
__global__ void k_zero(int n) {
    int i = blockIdx.x * blockDim.x + threadIdx.x;
    int stride = gridDim.x * blockDim.x;
    for (int j = i; j < n; j += stride) {
        g_deg[j]  = 0;
        g_spos[j] = 0.f;
        g_sneg[j] = 0.f;
    }
    if (i < HID) g_sumx[i] = 0.f;
}

// ---------------- edge pass: degree histogram (returns rank) + p3 scalars ----------------
__global__ void k_hist(const int* __restrict__ src, const int* __restrict__ dst,
                       const float* __restrict__ attr, int E) {
    int i = blockIdx.x * blockDim.x + threadIdx.x;
    int stride = gridDim.x * blockDim.x;
    for (int e = i; e < E; e += stride) {
        int d = dst[e];
        g_rank[e] = atomicAdd(&g_deg[d], 1);
        float a = attr[e];
        int s = src[e];
        if (a >= 0.f) atomicAdd(&g_spos[s], a);
        else          atomicAdd(&g_sneg[s], -a);
    }
}

// ---------------- 3-kernel parallel exclusive scan over degrees ----------------
__global__ void k_scan1(int n) {
    __shared__ int wsum[8];
    int idx = blockIdx.x * 256 + threadIdx.x;
    int lane = threadIdx.x & 31, wid = threadIdx.x >> 5;
    int v = (idx < n) ? g_deg[idx] : 0;
    int x = v;
    #pragma unroll
    for (int o = 1; o < 32; o <<= 1) {
        int t = __shfl_up_sync(0xffffffffu, x, o);
        if (lane >= o) x += t;
    }
    if (lane == 31) wsum[wid] = x;
    __syncthreads();
    if (wid == 0) {
        int w = (lane < 8) ? wsum[lane] : 0;
        #pragma unroll
        for (int o = 1; o < 8; o <<= 1) {
            int t = __shfl_up_sync(0xffffffffu, w, o);
            if (lane >= o) w += t;
        }
        if (lane < 8) wsum[lane] = w;
    }
    __syncthreads();
    int pre = wid ? wsum[wid - 1] : 0;
    if (idx < n) g_off[idx] = pre + x - v;          // block-local exclusive
    if (threadIdx.x == 255) g_bsum[blockIdx.x] = pre + x;  // block total
}

__global__ void k_scan2(int nb, int n) {
    __shared__ int wsum[16];
    int tid = threadIdx.x;
    int lane = tid & 31, wid = tid >> 5;
    int v = (tid < nb) ? g_bsum[tid] : 0;
    int x = v;
    #pragma unroll
    for (int o = 1; o < 32; o <<= 1) {
        int t = __shfl_up_sync(0xffffffffu, x, o);
        if (lane >= o) x += t;
    }
    if (lane == 31) wsum[wid] = x;
    __syncthreads();
    if (wid == 0) {
        int w = (lane < 16) ? wsum[lane] : 0;
        #pragma unroll
        for (int o = 1; o < 16; o <<= 1) {
            int t = __shfl_up_sync(0xffffffffu, w, o);
            if (lane >= o) w += t;
        }
        if (lane < 16) wsum[lane] = w;
    }
    __syncthreads();
    int pre = wid ? wsum[wid - 1] : 0;
    if (tid < nb) g_bsum[tid] = pre + x - v;        // exclusive block offsets
    if (tid == 0) g_off[n] = wsum[15];              // grand total
}

__global__ void k_scan3(int n) {
    int idx = blockIdx.x * 256 + threadIdx.x;
    if (idx < n) g_off[idx] += g_bsum[blockIdx.x];
}

// ---------------- atomic-free CSR fill using precomputed ranks ----------------
__global__ void k_scatter(const int* __restrict__ src, const int* __restrict__ dst, int E) {
    int i = blockIdx.x * blockDim.x + threadIdx.x;
    int stride = gridDim.x * blockDim.x;
    for (int e = i; e < E; e += stride) {
        int d = dst[e];
        g_adj[g_off[d] + g_rank[e]] = src[e];
    }
}

// ---------------- convert external fp32 x -> bf16 ----------------
__global__ void k_cvt(const float* __restrict__ x, int n4) {
    int i = blockIdx.x * blockDim.x + threadIdx.x;
    int stride = gridDim.x * blockDim.x;
    for (int j = i; j < n4; j += stride) {
        float4 f = ((const float4*)x)[j];
        __nv_bfloat162 a = __floats2bfloat162_rn(f.x, f.y);
        __nv_bfloat162 b = __floats2bfloat162_rn(f.z, f.w);
        uint2 u;
        u.x = *(unsigned*)&a;
        u.y = *(unsigned*)&b;
        ((uint2*)g_h0)[j] = u;
    }
}

// ---------------- gather-side aggregation: half-warp per node, bf16 rows ----------------
__global__ void k_aggr(int which, int n) {
    int node = (blockIdx.x * blockDim.x + threadIdx.x) >> 4;
    if (node >= n) return;
    int lane = threadIdx.x & 15;
    const __nv_bfloat16* xh = (which == 0) ? g_h0 : ((which == 1) ? g_h1 : g_h2);
    const uint2* xr = (const uint2*)xh;   // 4 bf16 per uint2; 16 uint2 per row
    int s = g_off[node], e = g_off[node + 1];
    float4 acc = make_float4(0.f, 0.f, 0.f, 0.f);
    int k = s;
    for (; k + 4 <= e; k += 4) {
        int j0 = g_adj[k], j1 = g_adj[k + 1], j2 = g_adj[k + 2], j3 = g_adj[k + 3];
        uint2 u0 = xr[j0 * 16 + lane];
        uint2 u1 = xr[j1 * 16 + lane];
        uint2 u2 = xr[j2 * 16 + lane];
        uint2 u3 = xr[j3 * 16 + lane];
        float2 a0 = bf2_to_f2(u0.x), b0 = bf2_to_f2(u0.y);
        float2 a1 = bf2_to_f2(u1.x), b1 = bf2_to_f2(u1.y);
        float2 a2 = bf2_to_f2(u2.x), b2 = bf2_to_f2(u2.y);
        float2 a3 = bf2_to_f2(u3.x), b3 = bf2_to_f2(u3.y);
        acc.x += (a0.x + a1.x) + (a2.x + a3.x);
        acc.y += (a0.y + a1.y) + (a2.y + a3.y);
        acc.z += (b0.x + b1.x) + (b2.x + b3.x);
        acc.w += (b0.y + b1.y) + (b2.y + b3.y);
    }
    for (; k < e; ++k) {
        uint2 u = xr[g_adj[k] * 16 + lane];
        float2 a = bf2_to_f2(u.x), b = bf2_to_f2(u.y);
        acc.x += a.x; acc.y += a.y; acc.z += b.x; acc.w += b.y;
    }
    ((float4*)g_aggr)[node * 16 + lane] = acc;
}

// ---------------- fused round GEMM: xnew = relu(p1 + aggr@W2 + p3) ----------------
#define FMA4(AS, BV, ACC) \
    ACC[0] = fmaf(AS, BV.x, ACC[0]); \
    ACC[1] = fmaf(AS, BV.y, ACC[1]); \
    ACC[2] = fmaf(AS, BV.z, ACC[2]); \
    ACC[3] = fmaf(AS, BV.w, ACC[3]);

// which_out: 0 -> g_h1 (bf16), 1 -> g_h2 (bf16), 2 -> g_x4 (fp32)
__global__ __launch_bounds__(256) void k_round(
    const float* __restrict__ xtag,
    const float* __restrict__ W1l, const float* __restrict__ W2l, const float* __restrict__ W4l,
    int which_out, int n, int do_sum)
{
    __shared__ __align__(16) float Bs[HID * HID];
    __shared__ __align__(16) float As[HID * HID];
    __shared__ float p1w[HID], p3p[HID], p3n[HID];
    __nv_bfloat16* outh = (which_out == 0) ? g_h1 : ((which_out == 1) ? g_h2 : (__nv_bfloat16*)0);

    int tid = threadIdx.x;
    for (int i = tid; i < HID * HID; i += 256) Bs[i] = W2l[i];
    if (tid < HID) {
        p1w[tid] = W1l[tid];
        float w = W4l[tid];
        p3p[tid] = fmaxf(w, 0.f);
        p3n[tid] = fmaxf(-w, 0.f);
    }
    __syncthreads();

    int tx = tid & 15, ty = tid >> 4;
    int h0 = tx * 4, m0 = ty * 4;
    float4* As4 = (float4*)As;
    float4* Bs4 = (float4*)Bs;
    float psum[4] = {0.f, 0.f, 0.f, 0.f};
    int ntiles = (n + 63) >> 6;

    for (int tile = blockIdx.x; tile < ntiles; tile += gridDim.x) {
        int base = tile << 6;
        const float4* Ag = (const float4*)g_aggr + base * 16;
        int avail4 = (((n - base) < 64) ? (n - base) : 64) * 16;
        for (int i = tid; i < 1024; i += 256)
            As4[i] = (i < avail4) ? Ag[i] : make_float4(0.f, 0.f, 0.f, 0.f);
        __syncthreads();

        float acc[4][4];
        #pragma unroll
        for (int i = 0; i < 4; ++i)
            #pragma unroll
            for (int j = 0; j < 4; ++j) acc[i][j] = 0.f;

        #pragma unroll
        for (int k4 = 0; k4 < 16; ++k4) {
            float4 b0 = Bs4[(4 * k4 + 0) * 16 + tx];
            float4 b1 = Bs4[(4 * k4 + 1) * 16 + tx];
            float4 b2 = Bs4[(4 * k4 + 2) * 16 + tx];
            float4 b3 = Bs4[(4 * k4 + 3) * 16 + tx];
            #pragma unroll
            for (int i = 0; i < 4; ++i) {
                float4 a = As4[(m0 + i) * 16 + k4];
                FMA4(a.x, b0, acc[i]);
                FMA4(a.y, b1, acc[i]);
                FMA4(a.z, b2, acc[i]);
                FMA4(a.w, b3, acc[i]);
            }
        }

        #pragma unroll
        for (int i = 0; i < 4; ++i) {
            int m = base + m0 + i;
            if (m < n) {
                float t = xtag[m], sp = g_spos[m], sn = g_sneg[m];
                float4 o;
                o.x = fmaxf(acc[i][0] + t * p1w[h0 + 0] + sp * p3p[h0 + 0] + sn * p3n[h0 + 0], 0.f);
                o.y = fmaxf(acc[i][1] + t * p1w[h0 + 1] + sp * p3p[h0 + 1] + sn * p3n[h0 + 1], 0.f);
                o.z = fmaxf(acc[i][2] + t * p1w[h0 + 2] + sp * p3p[h0 + 2] + sn * p3n[h0 + 2], 0.f);
                o.w = fmaxf(acc[i][3] + t * p1w[h0 + 3] + sp * p3p[h0 + 3] + sn * p3n[h0 + 3], 0.f);
                if (outh) {
                    __nv_bfloat162 pa = __floats2bfloat162_rn(o.x, o.y);
                    __nv_bfloat162 pb = __floats2bfloat162_rn(o.z, o.w);
                    uint2 u;
                    u.x = *(unsigned*)&pa;
                    u.y = *(unsigned*)&pb;
                    ((uint2*)outh)[m * 16 + tx] = u;
                } else {
                    ((float4*)g_x4)[m * 16 + tx] = o;
                }
                psum[0] += o.x; psum[1] += o.y; psum[2] += o.z; psum[3] += o.w;
            }
        }
        __syncthreads();
    }

    if (do_sum) {
        As[ty * HID + h0 + 0] = psum[0];
        As[ty * HID + h0 + 1] = psum[1];
        As[ty * HID + h0 + 2] = psum[2];
        As[ty * HID + h0 + 3] = psum[3];
        __syncthreads();
        if (tid < HID) {
            float s = 0.f;
            #pragma unroll
            for (int w = 0; w < 16; ++w) s += As[w * HID + tid];
            atomicAdd(&g_sumx[tid], s);
        }
    }
}

// ---------------- graph-pool scalar: c = sum_h relu((sumx @ W6)[h]) * W5[h] ----------------
__global__ void k_gpool(const float* __restrict__ W6, const float* __restrict__ W5) {
    int h = threadIdx.x;  // 64 threads
    float g = 0.f;
    #pragma unroll
    for (int k = 0; k < HID; ++k) g = fmaf(g_sumx[k], W6[k * HID + h], g);
    float v = fmaxf(g, 0.f) * W5[h];
    __shared__ float sh[HID];
    sh[h] = v;
    __syncthreads();
    if (h < 32) {
        float t = sh[h] + sh[h + 32];
        #pragma unroll
        for (int o = 16; o > 0; o >>= 1) t += __shfl_down_sync(0xffffffffu, t, o);
        if (h == 0) g_c[0] = t;
    }
}

// ---------------- final: Q[i] = c + sum_h relu((x @ W7)[i,h]) * W5[64+h] ----------------
__global__ __launch_bounds__(256) void k_final(
    const float* __restrict__ W7, const float* __restrict__ W5,
    float* __restrict__ Q, int n)
{
    __shared__ __align__(16) float Bs[HID * HID];
    __shared__ __align__(16) float As[HID * HID];
    __shared__ float w5s[HID];
    int tid = threadIdx.x;
    for (int i = tid; i < HID * HID; i += 256) Bs[i] = W7[i];
    if (tid < HID) w5s[tid] = W5[HID + tid];
    __syncthreads();

    int tx = tid & 15, ty = tid >> 4;
    int h0 = tx * 4, m0 = ty * 4;
    float4* As4 = (float4*)As;
    float4* Bs4 = (float4*)Bs;
    int ntiles = (n + 63) >> 6;
    float c = g_c[0];

    for (int tile = blockIdx.x; tile < ntiles; tile += gridDim.x) {
        int base = tile << 6;
        const float4* Ag = (const float4*)g_x4 + base * 16;
        int avail4 = (((n - base) < 64) ? (n - base) : 64) * 16;
        for (int i = tid; i < 1024; i += 256)
            As4[i] = (i < avail4) ? Ag[i] : make_float4(0.f, 0.f, 0.f, 0.f);
        __syncthreads();

        float acc[4][4];
        #pragma unroll
        for (int i = 0; i < 4; ++i)
            #pragma unroll
            for (int j = 0; j < 4; ++j) acc[i][j] = 0.f;

        #pragma unroll
        for (int k4 = 0; k4 < 16; ++k4) {
            float4 b0 = Bs4[(4 * k4 + 0) * 16 + tx];
            float4 b1 = Bs4[(4 * k4 + 1) * 16 + tx];
            float4 b2 = Bs4[(4 * k4 + 2) * 16 + tx];
            float4 b3 = Bs4[(4 * k4 + 3) * 16 + tx];
            #pragma unroll
            for (int i = 0; i < 4; ++i) {
                float4 a = As4[(m0 + i) * 16 + k4];
                FMA4(a.x, b0, acc[i]);
                FMA4(a.y, b1, acc[i]);
                FMA4(a.z, b2, acc[i]);
                FMA4(a.w, b3, acc[i]);
            }
        }

        #pragma unroll
        for (int i = 0; i < 4; ++i) {
            int m = base + m0 + i;
            float part = fmaxf(acc[i][0], 0.f) * w5s[h0 + 0]
                       + fmaxf(acc[i][1], 0.f) * w5s[h0 + 1]
                       + fmaxf(acc[i][2], 0.f) * w5s[h0 + 2]
                       + fmaxf(acc[i][3], 0.f) * w5s[h0 + 3];
            #pragma unroll
            for (int o = 8; o > 0; o >>= 1) part += __shfl_xor_sync(0xffffffffu, part, o);
            if (tx == 0 && m < n) Q[m] = c + part;
        }
        __syncthreads();
    }
}

// ---------------- launcher ----------------
extern "C" void kernel_launch(void* const* d_in, const int* in_sizes, int n_in,
                              void* d_out, int out_size) {
    const float* x     = (const float*)d_in[0];
    const float* xtag  = (const float*)d_in[1];
    const float* eattr = (const float*)d_in[2];
    const int*   eidx  = (const int*)d_in[3];
    const float* W1    = (const float*)d_in[4];
    const float* W2    = (const float*)d_in[5];
    const float* W4    = (const float*)d_in[6];
    const float* W5    = (const float*)d_in[7];
    const float* W6    = (const float*)d_in[8];
    const float* W7    = (const float*)d_in[9];
    float* Q = (float*)d_out;

    int n = in_sizes[1];
    int E = in_sizes[2];
    const int* src = eidx;
    const int* dst = eidx + E;

    int gb_n = (n + 255) / 256;
    int gb_e = (E + 255) / 256;
    int nb   = (n + 255) / 256;          // scan blocks (256 nodes each)
    int gb_hw = (n * 16 + 255) / 256;    // half-warp-per-node
    int gb_g = 782;                       // GEMM grid (grid-stride over 64-node tiles)
    int n4 = n * HID / 4;
    int gb_c = (n4 + 255) / 256;

    // CSR build + p3 scalars
    k_zero<<<gb_n, 256>>>(n);
    k_hist<<<gb_e, 256>>>(src, dst, eattr, E);
    k_scan1<<<nb, 256>>>(n);
    k_scan2<<<1, 512>>>(nb, n);
    k_scan3<<<nb, 256>>>(n);
    k_scatter<<<gb_e, 256>>>(src, dst, E);

    // input x -> bf16
    k_cvt<<<gb_c, 256>>>(x, n4);

    // 4 propagation rounds: h0 -> h1 -> h2 -> h1 -> x4(fp32)
    k_aggr<<<gb_hw, 256>>>(0, n);
    k_round<<<gb_g, 256>>>(xtag, W1 + 0 * HID, W2 + 0 * HID * HID, W4 + 0 * HID, 0, n, 0);
    k_aggr<<<gb_hw, 256>>>(1, n);
    k_round<<<gb_g, 256>>>(xtag, W1 + 1 * HID, W2 + 1 * HID * HID, W4 + 1 * HID, 1, n, 0);
    k_aggr<<<gb_hw, 256>>>(2, n);
    k_round<<<gb_g, 256>>>(xtag, W1 + 2 * HID, W2 + 2 * HID * HID, W4 + 2 * HID, 0, n, 0);
    k_aggr<<<gb_hw, 256>>>(1, n);
    k_round<<<gb_g, 256>>>(xtag, W1 + 3 * HID, W2 + 3 * HID * HID, W4 + 3 * HID, 2, n, 1);

    // readout
    k_gpool<<<1, HID>>>(W6, W5);
    k_final<<<gb_g, 256>>>(W7, W5, Q, n);
}